// round 1
// baseline (speedup 1.0000x reference)
#include <cuda_runtime.h>

// Problem constants (fixed by the dataset)
#define DD      4096      // in/out features
#define KB      128       // codebook size / number of bins
#define TROWS   16384     // B*S
#define ROWS    8         // rows per block
#define NBLK    (TROWS / ROWS)
#define NTHR    256

// CSR of assignments: perm[j'] lists j sorted by bin, offsets[b]..offsets[b+1]
__device__ int            g_offsets[KB + 1];
__device__ unsigned short g_perm[DD];

// ---------------------------------------------------------------------------
// Setup: deterministic counting sort of j by assignment bin.
// 1024 threads = 128 bins x 8 interleaved chunks (chunk c owns j = i*8+c),
// so warp lanes read consecutive/broadcast shared words (no bank conflicts).
// ---------------------------------------------------------------------------
__global__ void build_perm_kernel(const int* __restrict__ assign) {
    __shared__ int s_a[DD];
    __shared__ int s_wsum[32];
    int tid = threadIdx.x;

    for (int j = tid; j < DD; j += 1024) s_a[j] = assign[j] & (KB - 1);
    __syncthreads();

    int b = tid >> 3;   // bin 0..127
    int c = tid & 7;    // chunk 0..7

    int cnt = 0;
    for (int i = 0; i < DD / 8; i++) cnt += (s_a[i * 8 + c] == b);

    // exclusive scan of 1024 counts in (b,c)-lexicographic == tid order
    int l = tid & 31, w = tid >> 5;
    int v = cnt;
    #pragma unroll
    for (int d = 1; d < 32; d <<= 1) {
        int n = __shfl_up_sync(0xffffffffu, v, d);
        if (l >= d) v += n;
    }
    if (l == 31) s_wsum[w] = v;
    __syncthreads();
    if (w == 0) {
        int t = s_wsum[l];
        #pragma unroll
        for (int d = 1; d < 32; d <<= 1) {
            int n = __shfl_up_sync(0xffffffffu, t, d);
            if (l >= d) t += n;
        }
        s_wsum[l] = t;  // inclusive warp-total scan
    }
    __syncthreads();
    int excl = v - cnt + (w > 0 ? s_wsum[w - 1] : 0);

    if (c == 0)      g_offsets[b]  = excl;
    if (tid == 1023) g_offsets[KB] = excl + cnt;   // == DD

    int pos = excl;
    for (int i = 0; i < DD / 8; i++) {
        int j = i * 8 + c;
        if (s_a[j] == b) g_perm[pos++] = (unsigned short)j;
    }
}

// ---------------------------------------------------------------------------
// Main fused kernel. Per block: 8 rows.
//   stage x row -> smem (prefetch next row into regs)
//   y[128]  = segment-sum of x row by bin (2 threads per bin)
//   qm[128] = y @ QV[0:128,0:128]   (QV held in registers, reused all rows)
//   out[t,j] = qm[a_j] + bias[j]    (a_j/bias preloaded in regs, fixed slots)
// ---------------------------------------------------------------------------
__global__ void __launch_bounds__(NTHR, 2)
vq_main_kernel(const float* __restrict__ x,
               const float* __restrict__ qv,
               const int*   __restrict__ assign,
               const float* __restrict__ bias,
               float*       __restrict__ out) {
    __shared__ float4         s_x4[DD / 4];        // 16 KB staged x row
    __shared__ float          s_ypart[NTHR];
    __shared__ float          s_y[KB];
    __shared__ float          s_qmp[NTHR];
    __shared__ float          s_qm[KB];
    __shared__ unsigned short s_perm[DD];          // 8 KB
    __shared__ int            s_off[KB + 1];

    const int tid = threadIdx.x;
    const int h   = tid >> 7;    // half 0/1
    const int k   = tid & 127;   // bin / output column

    // block-wide metadata into shared
    for (int j = tid; j < DD; j += NTHR) s_perm[j] = g_perm[j];
    if (tid <= KB) s_off[tid] = g_offsets[tid];

    // QV[0:128, 0:128] into registers: thread owns column k, rows 64h..64h+63
    float qvr[64];
    #pragma unroll
    for (int i = 0; i < 64; i++)
        qvr[i] = qv[(h * 64 + i) * KB + k];

    // bias + assignments for this thread's fixed 16 output slots
    float4   biasr[4];
    unsigned ar[4];
    #pragma unroll
    for (int i = 0; i < 4; i++) {
        int e4 = i * NTHR + tid;                       // float4 slot in row
        biasr[i] = ((const float4*)bias)[e4];
        int4 a   = ((const int4*)assign)[e4];
        ar[i] = (unsigned)(a.x & 127)
              | ((unsigned)(a.y & 127) << 8)
              | ((unsigned)(a.z & 127) << 16)
              | ((unsigned)(a.w & 127) << 24);
    }

    const int t0 = blockIdx.x * ROWS;
    const float4* x4   = (const float4*)x;
    float4*       out4 = (float4*)out;

    // prefetch row 0
    float4 pre[4];
    #pragma unroll
    for (int i = 0; i < 4; i++)
        pre[i] = x4[(size_t)t0 * (DD / 4) + i * NTHR + tid];

    __syncthreads();
    const int lo = s_off[k] + h;
    const int hi = s_off[k + 1];

    for (int r = 0; r < ROWS; r++) {
        const int t = t0 + r;

        // stage current row
        #pragma unroll
        for (int i = 0; i < 4; i++) s_x4[i * NTHR + tid] = pre[i];
        __syncthreads();

        // prefetch next row while we compute
        if (r + 1 < ROWS) {
            #pragma unroll
            for (int i = 0; i < 4; i++)
                pre[i] = x4[(size_t)(t + 1) * (DD / 4) + i * NTHR + tid];
        }

        // ---- segment sum: y[b] = sum over j with a_j == b of x[t,j]
        const float* sx = (const float*)s_x4;
        float p = 0.f;
        for (int j = lo; j < hi; j += 2)
            p += sx[s_perm[j]];
        s_ypart[tid] = p;
        __syncthreads();
        if (tid < KB) s_y[tid] = s_ypart[tid] + s_ypart[tid + KB];
        __syncthreads();

        // ---- matvec: qm[k] = sum_{k'} y[k'] * QV[k',k]  (regs, float4 y reads)
        float acc = 0.f;
        const float4* sy4 = (const float4*)s_y;
        #pragma unroll
        for (int i4 = 0; i4 < 16; i4++) {
            float4 yv = sy4[h * 16 + i4];
            acc += yv.x * qvr[i4 * 4 + 0];
            acc += yv.y * qvr[i4 * 4 + 1];
            acc += yv.z * qvr[i4 * 4 + 2];
            acc += yv.w * qvr[i4 * 4 + 3];
        }
        s_qmp[tid] = acc;
        __syncthreads();
        if (tid < KB) s_qm[tid] = s_qmp[tid] + s_qmp[tid + KB];
        __syncthreads();

        // ---- output: out[t,j] = qm[a_j] + bias[j]
        #pragma unroll
        for (int i = 0; i < 4; i++) {
            unsigned a = ar[i];
            float4 o;
            o.x = s_qm[a & 255]         + biasr[i].x;
            o.y = s_qm[(a >> 8)  & 255] + biasr[i].y;
            o.z = s_qm[(a >> 16) & 255] + biasr[i].z;
            o.w = s_qm[(a >> 24)]       + biasr[i].w;
            out4[(size_t)t * (DD / 4) + i * NTHR + tid] = o;
        }
        // safe to overwrite s_x next iter: all threads passed the s_qm sync,
        // and the output phase touches only s_qm/registers.
    }
}

extern "C" void kernel_launch(void* const* d_in, const int* in_sizes, int n_in,
                              void* d_out, int out_size) {
    const float* x      = (const float*)d_in[0];
    const float* qv     = (const float*)d_in[1];
    const int*   assign = (const int*)d_in[2];
    const float* bias   = (const float*)d_in[3];
    float*       out    = (float*)d_out;

    build_perm_kernel<<<1, 1024>>>(assign);
    vq_main_kernel<<<NBLK, NTHR>>>(x, qv, assign, bias, out);
}

// round 2
// speedup vs baseline: 1.6366x; 1.6366x over previous
#include <cuda_runtime.h>

#define DD      4096
#define KB      128
#define TROWS   16384

// persistent device scratch (allowed: __device__ globals)
__device__ int            g_offsets[KB + 1];
__device__ unsigned short g_perm[DD];
__device__ float          g_Y[(size_t)TROWS * KB];   // 8 MB intermediate

// ---------------------------------------------------------------------------
// K0: deterministic counting sort of j by bin. Counts via int shared atomics
// (order-independent => deterministic), placement serial per 64-j group.
// ---------------------------------------------------------------------------
__global__ void k0_build(const int* __restrict__ assign) {
    __shared__ unsigned char s_a[DD];
    __shared__ int s_cnt[KB * 64];     // [bin][g], g = j>>6   (32 KB)
    __shared__ int s_warp[32];
    const int tid = threadIdx.x;

    for (int j = tid; j < DD; j += 1024) s_a[j] = (unsigned char)(assign[j] & 127);
    for (int c = tid; c < KB * 64; c += 1024) s_cnt[c] = 0;
    __syncthreads();

    #pragma unroll
    for (int i = 0; i < 4; i++) {
        int j = tid + 1024 * i;
        atomicAdd(&s_cnt[(int)s_a[j] * 64 + (j >> 6)], 1);
    }
    __syncthreads();

    // exclusive scan over the 8192 cells in (bin, group) order
    int loc[8]; int sum = 0;
    const int base = tid * 8;
    #pragma unroll
    for (int u = 0; u < 8; u++) { loc[u] = s_cnt[base + u]; sum += loc[u]; }

    int l = tid & 31, w = tid >> 5;
    int v = sum;
    #pragma unroll
    for (int d = 1; d < 32; d <<= 1) {
        int n = __shfl_up_sync(0xffffffffu, v, d);
        if (l >= d) v += n;
    }
    if (l == 31) s_warp[w] = v;
    __syncthreads();
    if (w == 0) {
        int t = s_warp[l];
        #pragma unroll
        for (int d = 1; d < 32; d <<= 1) {
            int n = __shfl_up_sync(0xffffffffu, t, d);
            if (l >= d) t += n;
        }
        s_warp[l] = t;
    }
    __syncthreads();
    int excl = v - sum + (w > 0 ? s_warp[w - 1] : 0);

    int run = excl;
    #pragma unroll
    for (int u = 0; u < 8; u++) { int c = loc[u]; s_cnt[base + u] = run; run += c; }
    __syncthreads();

    if (tid < KB)  g_offsets[tid] = s_cnt[tid * 64];
    if (tid == 0)  g_offsets[KB]  = DD;

    // placement: thread g owns all cells [*, g] exclusively -> race-free, deterministic
    if (tid < 64) {
        for (int q = 0; q < 64; q++) {
            int j = tid * 64 + q;
            int b = (int)s_a[j];
            int p = s_cnt[b * 64 + tid]++;
            g_perm[p] = (unsigned short)j;
        }
    }
}

// ---------------------------------------------------------------------------
// K1: Y[t, b] = sum_{j: a_j == b} x[t, j], 4 rows per batch, 4 batches per CTA.
// s_x4[swz(j)] = {x[t..t+3][j]}; swz XOR-spreads 16B bank-groups so both the
// staging STS.128 and the random gather LDS.128 approach full crossbar BW.
// ---------------------------------------------------------------------------
#define K1_SMEM (65536 + 8192 + 16384 + 640)

__device__ __forceinline__ int swz(int j) { return j ^ ((j >> 3) & 7); }

__global__ void __launch_bounds__(1024, 1)
k1_binsum(const float* __restrict__ x) {
    extern __shared__ char smem[];
    float4*         s_x4   = (float4*)smem;                           // [4096] 64 KB
    unsigned short* s_perm = (unsigned short*)(smem + 65536);         // [4096] 8 KB
    float4*         s_part = (float4*)(smem + 65536 + 8192);          // [1024] 16 KB
    int*            s_off  = (int*)(smem + 65536 + 8192 + 16384);     // [129]

    const int tid = threadIdx.x;

    for (int i = tid; i < DD / 2; i += 1024)
        ((unsigned*)s_perm)[i] = ((const unsigned*)g_perm)[i];
    if (tid <= KB) s_off[tid] = g_offsets[tid];
    __syncthreads();

    const int bin = tid >> 3, sub = tid & 7;
    const int lo = s_off[bin] + sub, hi = s_off[bin + 1];

    const int jA = 2 * tid;          // features 2t, 2t+1
    const int jB = 2 * tid + 2048;   // features 2t+2048, +2049
    const float2* x2 = (const float2*)x;
    const int t0 = blockIdx.x * 16;

    float2 v[8];   // [pairsel(2)][row(4)]
    #pragma unroll
    for (int r = 0; r < 4; r++) {
        v[r]     = x2[(size_t)(t0 + r) * 2048 + tid];
        v[4 + r] = x2[(size_t)(t0 + r) * 2048 + 1024 + tid];
    }

    #pragma unroll 1
    for (int b = 0; b < 4; b++) {
        const int tb = t0 + b * 4;
        __syncthreads();   // s_x free (prev gather done), s_part consumed

        s_x4[swz(jA)]     = make_float4(v[0].x, v[1].x, v[2].x, v[3].x);
        s_x4[swz(jA + 1)] = make_float4(v[0].y, v[1].y, v[2].y, v[3].y);
        s_x4[swz(jB)]     = make_float4(v[4].x, v[5].x, v[6].x, v[7].x);
        s_x4[swz(jB + 1)] = make_float4(v[4].y, v[5].y, v[6].y, v[7].y);

        if (b < 3) {   // prefetch next batch; latency hidden by gather below
            #pragma unroll
            for (int r = 0; r < 4; r++) {
                v[r]     = x2[(size_t)(tb + 4 + r) * 2048 + tid];
                v[4 + r] = x2[(size_t)(tb + 4 + r) * 2048 + 1024 + tid];
            }
        }
        __syncthreads();

        // segment gather: one LDS.128 delivers 4 rows of feature j
        float4 acc = make_float4(0.f, 0.f, 0.f, 0.f);
        for (int s = lo; s < hi; s += 8) {
            int j = (int)s_perm[s];
            float4 xv = s_x4[swz(j)];
            acc.x += xv.x; acc.y += xv.y; acc.z += xv.z; acc.w += xv.w;
        }
        s_part[bin * 8 + (sub ^ (bin & 7))] = acc;
        __syncthreads();

        if (tid < KB) {
            float4 t = make_float4(0.f, 0.f, 0.f, 0.f);
            #pragma unroll
            for (int u = 0; u < 8; u++) {
                float4 p = s_part[tid * 8 + (u ^ (tid & 7))];
                t.x += p.x; t.y += p.y; t.z += p.z; t.w += p.w;
            }
            g_Y[(size_t)(tb + 0) * KB + tid] = t.x;
            g_Y[(size_t)(tb + 1) * KB + tid] = t.y;
            g_Y[(size_t)(tb + 2) * KB + tid] = t.z;
            g_Y[(size_t)(tb + 3) * KB + tid] = t.w;
        }
    }
}

// ---------------------------------------------------------------------------
// K2: out[t, j] = (Y[t] @ QV)[a_j] + bias[j], 8 rows per CTA, processed as two
// groups of 4 rows so the random qm lookup is one LDS.128 per 4 rows.
// ---------------------------------------------------------------------------
__global__ void __launch_bounds__(256, 2)
k2_out(const float* __restrict__ qv,
       const int*   __restrict__ assign,
       const float* __restrict__ bias,
       float*       __restrict__ out) {
    __shared__ float  s_y[8 * KB];     // 4 KB
    __shared__ float4 s_qmp[256];      // 4 KB
    __shared__ float4 s_qm4[KB];       // 2 KB

    const int tid = threadIdx.x;
    const int h = tid >> 7, k = tid & 127;

    float qvr[64];
    #pragma unroll
    for (int i = 0; i < 64; i++) qvr[i] = qv[(h * 64 + i) * KB + k];

    float4 biasr[4]; unsigned ar[4];
    #pragma unroll
    for (int i = 0; i < 4; i++) {
        int e4 = i * 256 + tid;
        biasr[i] = ((const float4*)bias)[e4];
        int4 a = ((const int4*)assign)[e4];
        ar[i] = (unsigned)(a.x & 127)
              | ((unsigned)(a.y & 127) << 8)
              | ((unsigned)(a.z & 127) << 16)
              | ((unsigned)(a.w & 127) << 24);
    }

    const int t0 = blockIdx.x * 8;
    #pragma unroll
    for (int u = 0; u < 4; u++)
        s_y[u * 256 + tid] = g_Y[(size_t)t0 * KB + u * 256 + tid];
    __syncthreads();

    float4* out4 = (float4*)out;

    #pragma unroll 1
    for (int g = 0; g < 2; g++) {
        const float4* sy4 = (const float4*)(s_y + g * 4 * KB);

        // qm[r][k] for 4 rows; this thread covers k' in [64h, 64h+64)
        float4 acc = make_float4(0.f, 0.f, 0.f, 0.f);
        #pragma unroll
        for (int i4 = 0; i4 < 16; i4++) {
            float4 y0 = sy4[0 * 32 + h * 16 + i4];
            float4 y1 = sy4[1 * 32 + h * 16 + i4];
            float4 y2 = sy4[2 * 32 + h * 16 + i4];
            float4 y3 = sy4[3 * 32 + h * 16 + i4];
            float q0 = qvr[i4 * 4 + 0], q1 = qvr[i4 * 4 + 1];
            float q2 = qvr[i4 * 4 + 2], q3 = qvr[i4 * 4 + 3];
            acc.x += y0.x * q0 + y0.y * q1 + y0.z * q2 + y0.w * q3;
            acc.y += y1.x * q0 + y1.y * q1 + y1.z * q2 + y1.w * q3;
            acc.z += y2.x * q0 + y2.y * q1 + y2.z * q2 + y2.w * q3;
            acc.w += y3.x * q0 + y3.y * q1 + y3.z * q2 + y3.w * q3;
        }
        s_qmp[tid] = acc;
        __syncthreads();
        if (tid < KB) {
            float4 a0 = s_qmp[tid], a1 = s_qmp[tid + 128];
            s_qm4[tid] = make_float4(a0.x + a1.x, a0.y + a1.y,
                                     a0.z + a1.z, a0.w + a1.w);
        }
        __syncthreads();

        #pragma unroll
        for (int i = 0; i < 4; i++) {
            unsigned a = ar[i];
            float4 q0 = s_qm4[a & 255];
            float4 q1 = s_qm4[(a >> 8)  & 255];
            float4 q2 = s_qm4[(a >> 16) & 255];
            float4 q3 = s_qm4[(a >> 24)];
            float4 bb = biasr[i];
            size_t rowbase = (size_t)(t0 + g * 4) * 1024 + i * 256 + tid;
            out4[rowbase + 0 * 1024] = make_float4(q0.x + bb.x, q1.x + bb.y, q2.x + bb.z, q3.x + bb.w);
            out4[rowbase + 1 * 1024] = make_float4(q0.y + bb.x, q1.y + bb.y, q2.y + bb.z, q3.y + bb.w);
            out4[rowbase + 2 * 1024] = make_float4(q0.z + bb.x, q1.z + bb.y, q2.z + bb.z, q3.z + bb.w);
            out4[rowbase + 3 * 1024] = make_float4(q0.w + bb.x, q1.w + bb.y, q2.w + bb.z, q3.w + bb.w);
        }
        __syncthreads();   // before next group reuses s_qmp
    }
}

extern "C" void kernel_launch(void* const* d_in, const int* in_sizes, int n_in,
                              void* d_out, int out_size) {
    const float* x      = (const float*)d_in[0];
    const float* qv     = (const float*)d_in[1];
    const int*   assign = (const int*)d_in[2];
    const float* bias   = (const float*)d_in[3];
    float*       out    = (float*)d_out;

    // >48KB dynamic smem opt-in (not stream-ordered; safe to call every time)
    (void)cudaFuncSetAttribute(k1_binsum,
                               cudaFuncAttributeMaxDynamicSharedMemorySize,
                               K1_SMEM);

    k0_build<<<1, 1024>>>(assign);
    k1_binsum<<<TROWS / 16, 1024, K1_SMEM>>>(x);
    k2_out<<<TROWS / 8, 256>>>(qv, assign, bias, out);
}